// round 1
// baseline (speedup 1.0000x reference)
#include <cuda_runtime.h>
#include <math.h>

// Problem constants
#define Hs   128
#define Ws   128
#define Cs   64          // input channels
#define Os   64          // output channels
#define HW   (128 * 128)
#define K2s  9
#define Q    (Cs * K2s)  // 576

typedef unsigned long long u64;

// Scratch: offsets stored channel-last [pixel][18]  (4*16384*18 floats = 4.7MB)
__device__ float g_offset[4 * HW * 18];

// ---------------- packed f32x2 helpers (sm_100+) ----------------
__device__ __forceinline__ u64 pack2(float lo, float hi) {
    u64 r;
    asm("mov.b64 %0, {%1, %2};" : "=l"(r) : "f"(lo), "f"(hi));
    return r;
}
__device__ __forceinline__ void unpack2(u64 v, float& lo, float& hi) {
    asm("mov.b64 {%0, %1}, %2;" : "=f"(lo), "=f"(hi) : "l"(v));
}
__device__ __forceinline__ u64 fma2(u64 a, u64 b, u64 c) {
    u64 d;
    asm("fma.rn.f32x2 %0, %1, %2, %3;" : "=l"(d) : "l"(a), "l"(b), "l"(c));
    return d;
}

// ---------------- Kernel 1: offset conv (3x3, 64 -> 18, pad 1) ----------------
// offset[b][oc][h][w] = sum_{c,kh,kw} x[b][c][h+kh-1][w+kw-1] * wo[oc][c][kh][kw] + bo[oc]
// stored to g_offset[p*18 + oc]  (channel-last per pixel)
__global__ void __launch_bounds__(256, 1)
offset_conv_kernel(const float* __restrict__ x,
                   const float* __restrict__ wo,
                   const float* __restrict__ bo) {
    // smem weights: ws[(c*9 + k)*18 + oc]
    __shared__ float ws[Q * 18];
    for (int i = threadIdx.x; i < Q * 18; i += 256) {
        int q  = i / 18;
        int oc = i - q * 18;
        ws[i] = wo[oc * Q + q];
    }
    __syncthreads();

    int p = blockIdx.x * 256 + threadIdx.x;   // pixel id, 65536 total
    int w = p & 127;
    int h = (p >> 7) & 127;
    int b = p >> 14;
    const float* xb = x + (size_t)b * Cs * HW;

    u64 acc[9];
#pragma unroll
    for (int j = 0; j < 9; j++) acc[j] = pack2(bo[2 * j], bo[2 * j + 1]);

#pragma unroll 1
    for (int k = 0; k < 9; k++) {
        int kh = k / 3;
        int kw = k - kh * 3;
        int iy = h - 1 + kh;
        int ix = w - 1 + kw;
        float vf = (iy >= 0 && iy < Hs && ix >= 0 && ix < Ws) ? 1.0f : 0.0f;
        int cy = min(max(iy, 0), Hs - 1);
        int cx = min(max(ix, 0), Ws - 1);
        const float* xp = xb + cy * Ws + cx;
#pragma unroll 2
        for (int c = 0; c < Cs; c++) {
            float val = xp[c * HW] * vf;
            u64 s2 = pack2(val, val);
            const u64* wr = (const u64*)&ws[(c * 9 + k) * 18];
#pragma unroll
            for (int j = 0; j < 9; j++) acc[j] = fma2(s2, wr[j], acc[j]);
        }
    }

    u64* op = (u64*)&g_offset[(size_t)p * 18];
#pragma unroll
    for (int j = 0; j < 9; j++) op[j] = acc[j];
}

// ---------------- Kernel 2: deformable conv ----------------
// For each pixel: 9 bilinear sample positions (base grid + offset), gather all 64
// channels, inner product with w_deform reshaped [O][C*9] (q = c*9+k).
__global__ void __launch_bounds__(256, 1)
deform_conv_kernel(const float* __restrict__ x,
                   const float* __restrict__ wd,
                   const float* __restrict__ bd,
                   float* __restrict__ out) {
    extern __shared__ float ws[];   // [q][o] : 576*64 floats = 147456 B
    for (int i = threadIdx.x; i < Q * Os; i += 256) {
        int q = i >> 6;
        int o = i & 63;
        ws[i] = wd[o * Q + q];
    }
    __syncthreads();

    int p = blockIdx.x * 256 + threadIdx.x;
    int w = p & 127;
    int h = (p >> 7) & 127;
    int b = p >> 14;
    const float*  xb   = x + (size_t)b * Cs * HW;
    const float2* offp = (const float2*)&g_offset[(size_t)p * 18];

    u64 acc[32];
    const float2* bd2 = (const float2*)bd;
#pragma unroll
    for (int j = 0; j < 32; j++) { float2 t = bd2[j]; acc[j] = pack2(t.x, t.y); }

#pragma unroll 1
    for (int k = 0; k < 9; k++) {
        int kh = k / 3;
        int kw = k - kh * 3;
        float2 d = offp[k];                       // (dy, dx)
        float py = (float)(h - 1 + kh) + d.x;
        float px = (float)(w - 1 + kw) + d.y;
        float y0f = floorf(py), x0f = floorf(px);
        int y0 = (int)y0f, x0 = (int)x0f;
        int y1 = y0 + 1,   x1 = x0 + 1;
        float wy1 = py - y0f, wy0 = 1.0f - wy1;
        float wx1 = px - x0f, wx0 = 1.0f - wx1;
        float vy0 = (y0 >= 0 && y0 < Hs) ? 1.0f : 0.0f;
        float vy1 = (y1 >= 0 && y1 < Hs) ? 1.0f : 0.0f;
        float vx0 = (x0 >= 0 && x0 < Ws) ? 1.0f : 0.0f;
        float vx1 = (x1 >= 0 && x1 < Ws) ? 1.0f : 0.0f;
        float w00 = wy0 * wx0 * vy0 * vx0;
        float w01 = wy0 * wx1 * vy0 * vx1;
        float w10 = wy1 * wx0 * vy1 * vx0;
        float w11 = wy1 * wx1 * vy1 * vx1;
        int cy0 = min(max(y0, 0), Hs - 1), cy1 = min(max(y1, 0), Hs - 1);
        int cx0 = min(max(x0, 0), Ws - 1), cx1 = min(max(x1, 0), Ws - 1);
        int o00 = cy0 * Ws + cx0, o01 = cy0 * Ws + cx1;
        int o10 = cy1 * Ws + cx0, o11 = cy1 * Ws + cx1;

        const float* xp = xb;
#pragma unroll 2
        for (int c = 0; c < Cs; c++) {
            float s = fmaf(w00, xp[o00],
                      fmaf(w01, xp[o01],
                      fmaf(w10, xp[o10], w11 * xp[o11])));
            u64 s2 = pack2(s, s);
            const u64* wr = (const u64*)&ws[(c * 9 + k) * Os];
#pragma unroll
            for (int j = 0; j < 32; j++) acc[j] = fma2(s2, wr[j], acc[j]);
            xp += HW;
        }
    }

    float* op = out + (size_t)b * Os * HW + h * Ws + w;
#pragma unroll
    for (int j = 0; j < 32; j++) {
        float a0, a1;
        unpack2(acc[j], a0, a1);
        op[(2 * j) * HW]     = a0;
        op[(2 * j + 1) * HW] = a1;
    }
}

// ---------------- harness entry ----------------
extern "C" void kernel_launch(void* const* d_in, const int* in_sizes, int n_in,
                              void* d_out, int out_size) {
    const float* x  = (const float*)d_in[0];   // [4,64,128,128]
    const float* wo = (const float*)d_in[1];   // [18,64,3,3]
    const float* bo = (const float*)d_in[2];   // [18]
    const float* wd = (const float*)d_in[3];   // [64,64,3,3]
    const float* bd = (const float*)d_in[4];   // [64]
    float* out = (float*)d_out;                // [4,64,128,128]

    cudaFuncSetAttribute(deform_conv_kernel,
                         cudaFuncAttributeMaxDynamicSharedMemorySize,
                         Q * Os * (int)sizeof(float));

    offset_conv_kernel<<<256, 256>>>(x, wo, bo);
    deform_conv_kernel<<<256, 256, Q * Os * sizeof(float)>>>(x, wd, bd, out);
}